// round 14
// baseline (speedup 1.0000x reference)
#include <cuda_runtime.h>
#include <cstdint>

#define D_MODEL    1024
#define N_LEVELS   8
#define TPB        256               // 8 warps; warp = 16 rows; lane = half-row
#define NWARP      8
#define TILE_ROWS  128               // 8 warps x 16 rows
#define CHUNK_COLS 32
#define N_CHUNKS   32                // 1024 / 32
#define DEPTH      4
#define ROW_STRIDE_F 36              // 32 + 4 pad words -> conflict-free LDS.128
#define ROW_STRIDE_B (ROW_STRIDE_F * 4)          // 144 B
#define CHUNK_BUF_B (16 * ROW_STRIDE_B)          // 2304 B (16 rows x 32 cols)
#define HALF_L 3.9960f
#define LN_EPS 1e-5f
#define INV_D  (1.0f / 1024.0f)

// dynamic smem layout
#define OFF_BUFS 0                                    // 8 warps x 4 bufs x 2304 = 73728
#define OFF_GW   (NWARP * DEPTH * CHUNK_BUF_B)        // 73728: longlong2 gw[256][8] = 32768
#define OFF_CV   (OFF_GW + 256 * 8 * 16)              // 106496: float G[8], C[8]
#define OFF_TMP  (OFF_CV + 64)                        // 106560: float tmp[8][16]
#define SMEM_TOTAL (OFF_TMP + 512)                    // 107072 -> 2 CTAs/SM

typedef unsigned long long ull;

__device__ __forceinline__ ull pack2(float lo, float hi) {
    ull r; asm("mov.b64 %0, {%1, %2};" : "=l"(r) : "f"(lo), "f"(hi)); return r;
}
__device__ __forceinline__ void unpack2(ull p, float& lo, float& hi) {
    asm("mov.b64 {%0, %1}, %2;" : "=f"(lo), "=f"(hi) : "l"(p));
}
__device__ __forceinline__ ull fma2(ull a, ull b, ull c) {
    ull d; asm("fma.rn.f32x2 %0, %1, %2, %3;" : "=l"(d) : "l"(a), "l"(b), "l"(c)); return d;
}
__device__ __forceinline__ ull add2(ull a, ull b) {
    ull d; asm("add.rn.f32x2 %0, %1, %2;" : "=l"(d) : "l"(a), "l"(b)); return d;
}
__device__ __forceinline__ void cp16(uint32_t dst, const float* src) {
    asm volatile("cp.async.cg.shared.global [%0], [%1], 16;" :: "r"(dst), "l"(src));
}

__global__ __launch_bounds__(TPB, 2) void fsq_kernel(
    const float* __restrict__ x,     // [rows, 1024]
    const float* __restrict__ ln_w,  // [1024]
    const float* __restrict__ ln_b,  // [1024]
    const float* __restrict__ W,     // [8, 1024]
    float* __restrict__ out,         // [rows, 8]
    int rows)
{
    extern __shared__ char smem[];
    longlong2* gw    = (longlong2*)(smem + OFF_GW);   // [quad 0..255][level 0..7], 16B each
    float* sG        = (float*)(smem + OFF_CV);
    float* sC        = (float*)(smem + OFF_CV) + 8;
    float (*tmp)[16] = (float(*)[16])(smem + OFF_TMP);

    const int t = threadIdx.x;          // 0..255 ; preamble: thread t owns quad t
    const int w = t >> 5, L = t & 31;

    // ===== preamble pass 1: G_n = sum(ln_w*W[n]), C_n = sum(ln_b*W[n]) =====
    {
        float lw4[4], lb4[4], v[16];
        #pragma unroll
        for (int j = 0; j < 4; j++) { lw4[j] = ln_w[4*t + j]; lb4[j] = ln_b[4*t + j]; }
        #pragma unroll
        for (int n = 0; n < N_LEVELS; n++) {
            float sg = 0.f, sc = 0.f;
            #pragma unroll
            for (int j = 0; j < 4; j++) {
                float wv = W[n * D_MODEL + 4*t + j];
                sg = fmaf(lw4[j], wv, sg);
                sc = fmaf(lb4[j], wv, sc);
            }
            v[n] = sg; v[8 + n] = sc;
        }
        #pragma unroll
        for (int off = 16; off > 0; off >>= 1)
            #pragma unroll
            for (int k = 0; k < 16; k++)
                v[k] += __shfl_xor_sync(0xFFFFFFFFu, v[k], off);
        if (L == 0)
            #pragma unroll
            for (int k = 0; k < 16; k++) tmp[w][k] = v[k];
        __syncthreads();
        if (t < 16) {
            float s = 0.f;
            #pragma unroll
            for (int ww = 0; ww < NWARP; ww++) s += tmp[ww][t];
            if (t < 8) sG[t] = s; else sC[t - 8] = s;
        }
        __syncthreads();
    }
    // ===== preamble pass 2: centered g'[n][d] = ln_w[d]*W[n][d] - G_n/D =====
    {
        float lw4[4];
        #pragma unroll
        for (int j = 0; j < 4; j++) lw4[j] = ln_w[4*t + j];
        #pragma unroll
        for (int n = 0; n < N_LEVELS; n++) {
            float gn = sG[n] * INV_D;
            float g0 = fmaf(lw4[0], W[n * D_MODEL + 4*t + 0], -gn);
            float g1 = fmaf(lw4[1], W[n * D_MODEL + 4*t + 1], -gn);
            float g2 = fmaf(lw4[2], W[n * D_MODEL + 4*t + 2], -gn);
            float g3 = fmaf(lw4[3], W[n * D_MODEL + 4*t + 3], -gn);
            longlong2 p;
            p.x = (long long)pack2(g0, g1);
            p.y = (long long)pack2(g2, g3);
            gw[t * 8 + n] = p;
        }
    }
    __syncthreads();   // gw visible; last block barrier

    // ===== mainloop: per-warp private 4-deep cp.async pipeline =====
    const size_t tilebase = (size_t)blockIdx.x * TILE_ROWS;
    const uint32_t smem_u = (uint32_t)__cvta_generic_to_shared(smem);
    const uint32_t mybufs = smem_u + OFF_BUFS + w * DEPTH * CHUNK_BUF_B;

    // loader: lane covers 4 quads (qg*4+u) of row (L&15) in each 32-col chunk
    const int r_ld = L & 15;
    const int qg   = L >> 4;            // 0/1: which 64B half of the 128B chunk-slice
    size_t gr_ld = tilebase + 16 * w + r_ld;
    if (gr_ld >= (size_t)rows) gr_ld = rows - 1;       // clamp, never OOB
    const float* src0 = x + gr_ld * D_MODEL + qg * 16; // qg*4 quads = qg*16 floats
    const uint32_t dst0 = mybufs + r_ld * ROW_STRIDE_B + qg * 64;

    auto issue = [&](int chunk, int b) {
        const float* s0 = src0 + chunk * CHUNK_COLS;
        uint32_t d0 = dst0 + b * CHUNK_BUF_B;
        #pragma unroll
        for (int u = 0; u < 4; u++)
            cp16(d0 + u * 16, s0 + u * 4);
    };

    issue(0, 0);
    asm volatile("cp.async.commit_group;" ::: "memory");
    issue(1, 1);
    asm volatile("cp.async.commit_group;" ::: "memory");
    issue(2, 2);
    asm volatile("cp.async.commit_group;" ::: "memory");
    issue(3, 3);
    asm volatile("cp.async.commit_group;" ::: "memory");

    ull s2 = 0, q2 = 0, d2[N_LEVELS];
    #pragma unroll
    for (int n = 0; n < N_LEVELS; n++) d2[n] = 0;

    // consumer: lane = (row L&15, half L>>4); half h covers cols [h*16, h*16+16)
    const int r_cp = L & 15;
    const int hf   = L >> 4;
    const char* lrow = smem + OFF_BUFS + (size_t)w * DEPTH * CHUNK_BUF_B
                     + (size_t)r_cp * ROW_STRIDE_B + (size_t)hf * 64;

    for (int k = 0; k < N_CHUNKS; k++) {
        asm volatile("cp.async.wait_group 3;" ::: "memory");
        __syncwarp();

        const longlong2* trow = (const longlong2*)(lrow + (k & 3) * CHUNK_BUF_B);
        // lane's first col = k*32 + hf*16  ->  first quad = k*8 + hf*4
        const longlong2* gq   = gw + ((k * 8 + hf * 4) * 8);
        #pragma unroll
        for (int j = 0; j < 4; j++) {
            longlong2 xv = trow[j];
            ull a = (ull)xv.x, bb = (ull)xv.y;
            s2 = add2(s2, add2(a, bb));
            q2 = fma2(a, a, q2);
            q2 = fma2(bb, bb, q2);
            #pragma unroll
            for (int n = 0; n < N_LEVELS; n++) {
                longlong2 g = gq[j * 8 + n];          // per-phase uniform broadcast
                d2[n] = fma2(a,  (ull)g.x, d2[n]);
                d2[n] = fma2(bb, (ull)g.y, d2[n]);
            }
        }
        __syncwarp();                                 // all lanes done with buf k&3
        if (k + DEPTH < N_CHUNKS) issue(k + DEPTH, k & 3);
        asm volatile("cp.async.commit_group;" ::: "memory");  // uniform group count
    }

    // ===== epilogue: combine the two half-lanes (1 shfl step), finalize =====
    float v[10];
    {
        float lo, hi;
        unpack2(s2, lo, hi); v[0] = lo + hi;
        unpack2(q2, lo, hi); v[1] = lo + hi;
        #pragma unroll
        for (int n = 0; n < N_LEVELS; n++) { unpack2(d2[n], lo, hi); v[2 + n] = lo + hi; }
    }
    #pragma unroll
    for (int kk = 0; kk < 10; kk++)
        v[kk] += __shfl_xor_sync(0xFFFFFFFFu, v[kk], 16);

    if (L < 16) {
        size_t grow = tilebase + 16 * w + L;
        if (grow < (size_t)rows) {
            float mean = v[0] * INV_D;
            float var  = fmaf(v[1], INV_D, -mean * mean);
            float rstd = rsqrtf(var + LN_EPS);
            float o[N_LEVELS];
            #pragma unroll
            for (int n = 0; n < N_LEVELS; n++) {
                float z = fmaf(rstd, v[2 + n], sC[n]);   // mean folded into centered g'
                o[n] = rintf(HALF_L * tanhf(z));
            }
            float4* op = (float4*)(out + grow * N_LEVELS);
            op[0] = make_float4(o[0], o[1], o[2], o[3]);
            op[1] = make_float4(o[4], o[5], o[6], o[7]);
        }
    }
}

extern "C" void kernel_launch(void* const* d_in, const int* in_sizes, int n_in,
                              void* d_out, int out_size) {
    const float* regrs = (const float*)d_in[0];
    const float* ln_w  = (const float*)d_in[1];
    const float* ln_b  = (const float*)d_in[2];
    const float* W     = (const float*)d_in[3];
    float* out = (float*)d_out;

    int rows = in_sizes[0] / D_MODEL;                  // 32768
    int grid = (rows + TILE_ROWS - 1) / TILE_ROWS;     // 256

    cudaFuncSetAttribute(fsq_kernel,
                         cudaFuncAttributeMaxDynamicSharedMemorySize, SMEM_TOTAL);
    fsq_kernel<<<grid, TPB, SMEM_TOTAL>>>(regrs, ln_w, ln_b, W, out, rows);
}

// round 15
// speedup vs baseline: 2.0435x; 2.0435x over previous
#include <cuda_runtime.h>
#include <cstdint>

#define D_MODEL    1024
#define N_LEVELS   8
#define TPB        224               // 7 warps; lane = one full row; warp = 32 rows
#define NWARP      7
#define CHUNK_COLS 32
#define N_CHUNKS   32                // 1024 / 32
#define NBUF       6                 // ring of 6 chunk buffers per warp
#define ROW_STRIDE_F 36              // 32 + 4 pad -> conflict-free LDS.128 phases
#define ROW_STRIDE_B (ROW_STRIDE_F * 4)          // 144 B
#define CHUNK_BUF_B (32 * ROW_STRIDE_B)          // 4608 B (32 rows x 32 cols)
#define HALF_L 3.9960f
#define LN_EPS 1e-5f
#define INV_D  (1.0f / 1024.0f)

// dynamic smem layout
#define OFF_BUFS 0                                    // 7 x 6 x 4608 = 193536
#define OFF_GW   (NWARP * NBUF * CHUNK_BUF_B)         // 193536: longlong2 gw[256][8] = 32768
#define OFF_CV   (OFF_GW + 256 * 8 * 16)              // 226304: float G[8], C[8]
#define OFF_TMP  (OFF_CV + 64)                        // 226368: float tmp[7][16]
#define SMEM_TOTAL (OFF_TMP + 448)                    // 226816 B (<= 232448 carveout)

typedef unsigned long long ull;

__device__ __forceinline__ ull pack2(float lo, float hi) {
    ull r; asm("mov.b64 %0, {%1, %2};" : "=l"(r) : "f"(lo), "f"(hi)); return r;
}
__device__ __forceinline__ void unpack2(ull p, float& lo, float& hi) {
    asm("mov.b64 {%0, %1}, %2;" : "=f"(lo), "=f"(hi) : "l"(p));
}
__device__ __forceinline__ ull fma2(ull a, ull b, ull c) {
    ull d; asm("fma.rn.f32x2 %0, %1, %2, %3;" : "=l"(d) : "l"(a), "l"(b), "l"(c)); return d;
}
__device__ __forceinline__ ull add2(ull a, ull b) {
    ull d; asm("add.rn.f32x2 %0, %1, %2;" : "=l"(d) : "l"(a), "l"(b)); return d;
}
__device__ __forceinline__ void cp16(uint32_t dst, const float* src) {
    asm volatile("cp.async.cg.shared.global [%0], [%1], 16;" :: "r"(dst), "l"(src));
}

__global__ __launch_bounds__(TPB, 1) void fsq_kernel(
    const float* __restrict__ x,     // [rows, 1024]
    const float* __restrict__ ln_w,  // [1024]
    const float* __restrict__ ln_b,  // [1024]
    const float* __restrict__ W,     // [8, 1024]
    float* __restrict__ out,         // [rows, 8]
    int rows)
{
    extern __shared__ char smem[];
    longlong2* gw    = (longlong2*)(smem + OFF_GW);   // [quad 0..255][level 0..7], 16B each
    float* sG        = (float*)(smem + OFF_CV);
    float* sC        = (float*)(smem + OFF_CV) + 8;
    float (*tmp)[16] = (float(*)[16])(smem + OFF_TMP);

    const int t = threadIdx.x;          // 0..223
    const int w = t >> 5, L = t & 31;

    // ===== preamble pass 1: G_n = sum(ln_w*W[n]), C_n = sum(ln_b*W[n]) =====
    {
        float v[16];
        #pragma unroll
        for (int k = 0; k < 16; k++) v[k] = 0.f;
        for (int q = t; q < 256; q += TPB) {          // quads t (and t+224 for t<32)
            float lw4[4], lb4[4];
            #pragma unroll
            for (int j = 0; j < 4; j++) { lw4[j] = ln_w[4*q + j]; lb4[j] = ln_b[4*q + j]; }
            #pragma unroll
            for (int n = 0; n < N_LEVELS; n++) {
                #pragma unroll
                for (int j = 0; j < 4; j++) {
                    float wv = W[n * D_MODEL + 4*q + j];
                    v[n]     = fmaf(lw4[j], wv, v[n]);
                    v[8 + n] = fmaf(lb4[j], wv, v[8 + n]);
                }
            }
        }
        #pragma unroll
        for (int off = 16; off > 0; off >>= 1)
            #pragma unroll
            for (int k = 0; k < 16; k++)
                v[k] += __shfl_xor_sync(0xFFFFFFFFu, v[k], off);
        if (L == 0)
            #pragma unroll
            for (int k = 0; k < 16; k++) tmp[w][k] = v[k];
        __syncthreads();
        if (t < 16) {
            float s = 0.f;
            #pragma unroll
            for (int ww = 0; ww < NWARP; ww++) s += tmp[ww][t];
            if (t < 8) sG[t] = s; else sC[t - 8] = s;
        }
        __syncthreads();
    }
    // ===== preamble pass 2: centered g'[n][d] = ln_w[d]*W[n][d] - G_n/D =====
    for (int q = t; q < 256; q += TPB) {
        float lw4[4];
        #pragma unroll
        for (int j = 0; j < 4; j++) lw4[j] = ln_w[4*q + j];
        #pragma unroll
        for (int n = 0; n < N_LEVELS; n++) {
            float gn = sG[n] * INV_D;
            float g0 = fmaf(lw4[0], W[n * D_MODEL + 4*q + 0], -gn);
            float g1 = fmaf(lw4[1], W[n * D_MODEL + 4*q + 1], -gn);
            float g2 = fmaf(lw4[2], W[n * D_MODEL + 4*q + 2], -gn);
            float g3 = fmaf(lw4[3], W[n * D_MODEL + 4*q + 3], -gn);
            longlong2 p;
            p.x = (long long)pack2(g0, g1);
            p.y = (long long)pack2(g2, g3);
            gw[q * 8 + n] = p;
        }
    }
    __syncthreads();   // gw visible; last block barrier

    // ===== mainloop: warp gid owns rows [gid*32, gid*32+32) =====
    const int gid = blockIdx.x * NWARP + w;
    const int n_groups = (rows + 31) >> 5;
    if (gid < n_groups) {
        const size_t rowbase = (size_t)gid * 32;
        const uint32_t smem_u = (uint32_t)__cvta_generic_to_shared(smem);
        const uint32_t mybufs = smem_u + OFF_BUFS + w * NBUF * CHUNK_BUF_B;

        // loader: lane covers quad (L&7) of rows (L>>3)+4u, u=0..7
        const int qd = L & 7;
        const int rb = L >> 3;
        size_t gr0 = rowbase + rb;
        if (gr0 >= (size_t)rows) gr0 = rows - 1;
        const float* src0 = x + gr0 * D_MODEL + qd * 4;
        const uint32_t dst0 = mybufs + rb * ROW_STRIDE_B + qd * 16;

        auto issue = [&](int chunk, int b) {
            const float* s0 = src0 + chunk * CHUNK_COLS;
            uint32_t d0 = dst0 + b * CHUNK_BUF_B;
            #pragma unroll
            for (int u = 0; u < 8; u++)
                cp16(d0 + u * 4 * ROW_STRIDE_B, s0 + (size_t)u * 4 * D_MODEL);
        };

        #pragma unroll
        for (int c = 0; c < NBUF; c++) {
            issue(c, c);
            asm volatile("cp.async.commit_group;" ::: "memory");
        }

        ull s2 = 0, q2 = 0, d2[N_LEVELS];
        #pragma unroll
        for (int n = 0; n < N_LEVELS; n++) d2[n] = 0;

        const char* lrow = smem + OFF_BUFS + (size_t)w * NBUF * CHUNK_BUF_B
                         + (size_t)L * ROW_STRIDE_B;

        for (int i = 0; i < N_CHUNKS / 2; i++) {
            const int c0 = 2 * i, c1 = 2 * i + 1;
            const int b0 = c0 % NBUF, b1 = c1 % NBUF;

            asm volatile("cp.async.wait_group 4;" ::: "memory");
            __syncwarp();

            // batch-load both chunks' x into registers (MLP 16)
            const longlong2* ra = (const longlong2*)(lrow + b0 * CHUNK_BUF_B);
            const longlong2* rbp = (const longlong2*)(lrow + b1 * CHUNK_BUF_B);
            longlong2 xa[8], xb[8];
            #pragma unroll
            for (int j = 0; j < 8; j++) { xa[j] = ra[j]; xb[j] = rbp[j]; }

            const longlong2* ga = gw + c0 * 64;   // quads c0*8 .. c0*8+7
            const longlong2* gb = gw + c1 * 64;
            #pragma unroll
            for (int j = 0; j < 8; j++) {
                ull a0 = (ull)xa[j].x, a1 = (ull)xa[j].y;
                ull e0 = (ull)xb[j].x, e1 = (ull)xb[j].y;
                s2 = add2(s2, add2(add2(a0, a1), add2(e0, e1)));
                q2 = fma2(a0, a0, q2);
                q2 = fma2(a1, a1, q2);
                q2 = fma2(e0, e0, q2);
                q2 = fma2(e1, e1, q2);
                #pragma unroll
                for (int n = 0; n < N_LEVELS; n++) {
                    longlong2 g0 = ga[j * 8 + n];         // full-warp broadcast LDS
                    longlong2 g1 = gb[j * 8 + n];
                    ull d = d2[n];
                    d = fma2(a0, (ull)g0.x, d);
                    d = fma2(a1, (ull)g0.y, d);
                    d = fma2(e0, (ull)g1.x, d);
                    d = fma2(e1, (ull)g1.y, d);
                    d2[n] = d;
                }
            }
            __syncwarp();                                 // lanes done with bufs b0,b1
            const int n0 = c0 + NBUF, n1 = c1 + NBUF;
            if (n0 < N_CHUNKS) issue(n0, b0);
            asm volatile("cp.async.commit_group;" ::: "memory");
            if (n1 < N_CHUNKS) issue(n1, b1);
            asm volatile("cp.async.commit_group;" ::: "memory");
        }

        // ===== epilogue: per-lane finalize (lane = row), no reduction =====
        size_t grow = rowbase + L;
        if (grow < (size_t)rows) {
            float lo, hi;
            unpack2(s2, lo, hi); float sum   = lo + hi;
            unpack2(q2, lo, hi); float sumsq = lo + hi;
            float mean = sum * INV_D;
            float var  = fmaf(sumsq, INV_D, -mean * mean);
            float rstd = rsqrtf(var + LN_EPS);
            float o[N_LEVELS];
            #pragma unroll
            for (int n = 0; n < N_LEVELS; n++) {
                unpack2(d2[n], lo, hi);
                float z = fmaf(rstd, lo + hi, sC[n]);     // mean folded into centered g'
                o[n] = rintf(HALF_L * tanhf(z));
            }
            float4* op = (float4*)(out + grow * N_LEVELS);
            op[0] = make_float4(o[0], o[1], o[2], o[3]);
            op[1] = make_float4(o[4], o[5], o[6], o[7]);
        }
    }
}

extern "C" void kernel_launch(void* const* d_in, const int* in_sizes, int n_in,
                              void* d_out, int out_size) {
    const float* regrs = (const float*)d_in[0];
    const float* ln_w  = (const float*)d_in[1];
    const float* ln_b  = (const float*)d_in[2];
    const float* W     = (const float*)d_in[3];
    float* out = (float*)d_out;

    int rows = in_sizes[0] / D_MODEL;                  // 32768
    int n_groups = (rows + 31) / 32;                   // 1024
    int grid = (n_groups + NWARP - 1) / NWARP;         // 147 -> 147? 1024/7 = 146.3 -> 147
    if (grid > 148) grid = 148;

    cudaFuncSetAttribute(fsq_kernel,
                         cudaFuncAttributeMaxDynamicSharedMemorySize, SMEM_TOTAL);
    fsq_kernel<<<grid, TPB, SMEM_TOTAL>>>(regrs, ln_w, ln_b, W, out, rows);
}